// round 9
// baseline (speedup 1.0000x reference)
#include <cuda_runtime.h>
#include <cstdint>
#include <cstddef>

// Problem constants
#define NVOBJ 2048
#define KK    8
#define LL    10
#define DD    300
#define FF    512
#define NOBJ  4096
#define TM    3
#define BSEQ  (NVOBJ*KK)        // 16384
#define BLTOT (BSEQ*LL)         // 163840
#define G3D   (3*DD)            // 900
#define ZDIM  (4*DD)            // 1200
#define CAT2  (DD+FF)           // 812
#define D2    (2*DD)            // 600
#define D4    (DD/4)            // 75

// ---------------- scratch (device globals; no allocation) ----------------
__device__ float g_xg[(size_t)2*BLTOT*G3D];   // both dirs, packed time-major
__device__ float g_xp[(size_t)2*BLTOT*DD];
__device__ float g_hg[(size_t)2*BSEQ*G3D];
__device__ float g_h[2*BSEQ*DD];              // fwd rows [0,BSEQ), bwd [BSEQ,2BSEQ)
__device__ float g_facts[BSEQ*DD];
__device__ float g_feats[NVOBJ*FF];
__device__ float g_q[NVOBJ*DD];
__device__ float g_m[NVOBJ*DD];
__device__ float g_z[(size_t)BSEQ*ZDIM];
__device__ float g_h1[(size_t)BSEQ*FF];
__device__ float g_gate[BSEQ];
__device__ float g_U2i[D2*DD];      // interleaved (Ur_d, Uh_d) rows
__device__ float g_W2i[D2*DD];      // interleaved (Wr_d, Wh_d) rows
__device__ float g_b2i[D2];
__device__ float g_fW2[(size_t)BSEQ*D2];
__device__ float g_attnA[NVOBJ*DD];
__device__ float g_attnB[NVOBJ*DD];
__device__ float g_cat[NVOBJ*G3D];
__device__ float g_cat2[NVOBJ*CAT2];
__device__ float g_upd[NVOBJ*FF];
// packing metadata
__device__ int g_cnt[16];
__device__ int g_basec[16];
__device__ int g_cursor[16];
__device__ int g_nact[LL];        // n_active[t]
__device__ int g_nact2[2*LL];     // for merged input proj (idx = row>>14, t=idx%10)
__device__ int g_nactpair[2*LL];  // [2t],[2t+1] = nact[t]
__device__ int g_perm[BSEQ];

__device__ __forceinline__ float sigm(float x) { return 1.f / (1.f + expf(-x)); }

__device__ __forceinline__ void mma_tf32(float c[4], uint32_t a0, uint32_t a1,
                                         uint32_t a2, uint32_t a3,
                                         uint32_t b0, uint32_t b1)
{
    asm volatile(
        "mma.sync.aligned.m16n8k8.row.col.f32.tf32.tf32.f32 "
        "{%0,%1,%2,%3}, {%4,%5,%6,%7}, {%8,%9}, {%0,%1,%2,%3};"
        : "+f"(c[0]), "+f"(c[1]), "+f"(c[2]), "+f"(c[3])
        : "r"(a0), "r"(a1), "r"(a2), "r"(a3), "r"(b0), "r"(b1));
}

__device__ __forceinline__ void cp_async16(uint32_t saddr, const void* g, bool valid)
{
    int sz = valid ? 16 : 0;
    asm volatile("cp.async.cg.shared.global [%0], [%1], 16, %2;\n"
                 :: "r"(saddr), "l"(g), "r"(sz));
}
__device__ __forceinline__ void cp_commit() {
    asm volatile("cp.async.commit_group;\n" ::: "memory");
}

#define SA 36   // padded k-stride (words)

// Shared mainloop macro body implemented via inline function pattern:
// (duplicated in both GEMM kernels for simplicity)

// ---------------- tensor-core NT GEMM: C = act(A(M,K) @ B(N,K)^T + bias) --
// act: 0=none, 1=tanh, 2=relu. Dual-B: rows >= mhalf use B2/bias2.
// limits: block exits when (bm & ((1<<limshift)-1)) >= limits[bm>>limshift].
__global__ __launch_bounds__(256) void gemm_nt_tc(
    const float* __restrict__ A, const float* __restrict__ B,
    const float* __restrict__ bias, float* __restrict__ C,
    int M, int N, int K, int act,
    const int* __restrict__ limits, int limshift,
    const float* __restrict__ B2, const float* __restrict__ bias2, int mhalf)
{
    __shared__ uint32_t As[2][128 * SA];
    __shared__ uint32_t Bs[2][64 * SA];

    const int bm = blockIdx.y * 128;
    const int bn = blockIdx.x * 64;
    if (limits) {
        int lim = __ldg(limits + (bm >> limshift));
        if ((bm & ((1 << limshift) - 1)) >= lim) return;
    }
    const float* Bsel = (B2 && bm >= mhalf) ? B2 : B;
    const float* biassel = (B2 && bm >= mhalf) ? bias2 : bias;

    const int tid = threadIdx.x;
    const int lane = tid & 31;
    const int warp = tid >> 5;
    const int wm = warp & 3;
    const int wn = warp >> 2;
    const int g = lane >> 2;
    const int c = lane & 3;
    const int row0 = wm * 32;
    const int col0 = wn * 32;

    float acc[2][4][4];
    #pragma unroll
    for (int i = 0; i < 2; i++)
        #pragma unroll
        for (int j = 0; j < 4; j++)
            #pragma unroll
            for (int l = 0; l < 4; l++) acc[i][j][l] = 0.f;

    const int ar = tid >> 1;
    const int akq = (tid & 1) * 16;
    const int brow = tid >> 2;
    const int bkq = (tid & 3) * 8;

    const int gmA = bm + ar;
    const float* Arow = A + (size_t)(gmA < M ? gmA : M - 1) * K;
    const int gnB = bn + brow;
    const float* Brow = Bsel + (size_t)(gnB < N ? gnB : N - 1) * K;

    const int ntiles = (K + 31) / 32;

    auto stage = [&](int s, int k0) {
        #pragma unroll
        for (int i = 0; i < 4; ++i) {
            int gk = k0 + akq + i * 4;
            bool v = (gmA < M) && (gk + 3 < K);
            cp_async16((uint32_t)__cvta_generic_to_shared(&As[s][ar * SA + akq + i * 4]),
                       Arow + gk, v);
        }
        #pragma unroll
        for (int i = 0; i < 2; ++i) {
            int gk = k0 + bkq + i * 4;
            bool v = (gnB < N) && (gk + 3 < K);
            cp_async16((uint32_t)__cvta_generic_to_shared(&Bs[s][brow * SA + bkq + i * 4]),
                       Brow + gk, v);
        }
    };

    stage(0, 0);
    cp_commit();
    int buf = 0;

    for (int it = 0; it < ntiles; ++it) {
        if (it + 1 < ntiles) {
            stage(buf ^ 1, (it + 1) * 32);
            cp_commit();
            asm volatile("cp.async.wait_group 1;\n" ::: "memory");
        } else {
            asm volatile("cp.async.wait_group 0;\n" ::: "memory");
        }
        __syncthreads();

        #pragma unroll
        for (int ks = 0; ks < 4; ++ks) {
            const int kbase = ks * 8;
            uint32_t a[2][4];
            #pragma unroll
            for (int mm = 0; mm < 2; ++mm) {
                int base = (row0 + mm * 16 + g) * SA + kbase;
                a[mm][0] = As[buf][base + c];
                a[mm][1] = As[buf][base + 8 * SA + c];
                a[mm][2] = As[buf][base + c + 4];
                a[mm][3] = As[buf][base + 8 * SA + c + 4];
            }
            #pragma unroll
            for (int nn = 0; nn < 4; ++nn) {
                int rb = (col0 + nn * 8 + g) * SA + kbase;
                uint32_t b0 = Bs[buf][rb + c];
                uint32_t b1 = Bs[buf][rb + c + 4];
                #pragma unroll
                for (int mm = 0; mm < 2; ++mm) {
                    mma_tf32(acc[mm][nn], a[mm][0], a[mm][1], a[mm][2], a[mm][3],
                             b0, b1);
                }
            }
        }
        __syncthreads();
        buf ^= 1;
    }

    #pragma unroll
    for (int mm = 0; mm < 2; ++mm) {
        int gm0 = bm + row0 + mm * 16 + g;
        #pragma unroll
        for (int nn = 0; nn < 4; ++nn) {
            int gn = bn + col0 + nn * 8 + 2 * c;
            if (gn >= N) continue;
            float b0 = 0.f, b1 = 0.f;
            if (biassel) { b0 = biassel[gn]; b1 = biassel[gn + 1]; }
            #pragma unroll
            for (int half = 0; half < 2; ++half) {
                int gm = gm0 + half * 8;
                if (gm >= M) continue;
                float v0 = acc[mm][nn][half * 2 + 0] + b0;
                float v1 = acc[mm][nn][half * 2 + 1] + b1;
                if (act == 1) { v0 = tanhf(v0); v1 = tanhf(v1); }
                else if (act == 2) { v0 = fmaxf(v0, 0.f); v1 = fmaxf(v1, 0.f); }
                *reinterpret_cast<float2*>(C + (size_t)gm * N + gn) =
                    make_float2(v0, v1);
            }
        }
    }
}

// ---------------- AGRU-fused GEMM step ----------------
// hU2 = attn_in @ U2i^T (N=600, pair-interleaved), epilogue applies AGRU update:
// h_out[v,d] = g*tanh(fW2h + r*uh) + (1-g)*attn_in[v,d], r = sigm(fW2r + ur)
__global__ __launch_bounds__(256) void gemm_agru(
    const float* __restrict__ Ain, const float* __restrict__ U2i,
    const float* __restrict__ fW2, const float* __restrict__ gate,
    float* __restrict__ Hout, int t)
{
    __shared__ uint32_t As[2][128 * SA];
    __shared__ uint32_t Bs[2][64 * SA];

    const int M = NVOBJ, N = D2, K = DD;
    const int bm = blockIdx.y * 128;
    const int bn = blockIdx.x * 64;
    const int tid = threadIdx.x;
    const int lane = tid & 31;
    const int warp = tid >> 5;
    const int wm = warp & 3;
    const int wn = warp >> 2;
    const int g = lane >> 2;
    const int c = lane & 3;
    const int row0 = wm * 32;
    const int col0 = wn * 32;

    float acc[2][4][4];
    #pragma unroll
    for (int i = 0; i < 2; i++)
        #pragma unroll
        for (int j = 0; j < 4; j++)
            #pragma unroll
            for (int l = 0; l < 4; l++) acc[i][j][l] = 0.f;

    const int ar = tid >> 1;
    const int akq = (tid & 1) * 16;
    const int brow = tid >> 2;
    const int bkq = (tid & 3) * 8;

    const int gmA = bm + ar;
    const float* Arow = Ain + (size_t)gmA * K;
    const int gnB = bn + brow;
    const float* Brow = U2i + (size_t)(gnB < N ? gnB : N - 1) * K;

    const int ntiles = (K + 31) / 32;   // 10

    auto stage = [&](int s, int k0) {
        #pragma unroll
        for (int i = 0; i < 4; ++i) {
            int gk = k0 + akq + i * 4;
            bool v = (gk + 3 < K);
            cp_async16((uint32_t)__cvta_generic_to_shared(&As[s][ar * SA + akq + i * 4]),
                       Arow + gk, v);
        }
        #pragma unroll
        for (int i = 0; i < 2; ++i) {
            int gk = k0 + bkq + i * 4;
            bool v = (gnB < N) && (gk + 3 < K);
            cp_async16((uint32_t)__cvta_generic_to_shared(&Bs[s][brow * SA + bkq + i * 4]),
                       Brow + gk, v);
        }
    };

    stage(0, 0);
    cp_commit();
    int buf = 0;

    for (int it = 0; it < ntiles; ++it) {
        if (it + 1 < ntiles) {
            stage(buf ^ 1, (it + 1) * 32);
            cp_commit();
            asm volatile("cp.async.wait_group 1;\n" ::: "memory");
        } else {
            asm volatile("cp.async.wait_group 0;\n" ::: "memory");
        }
        __syncthreads();

        #pragma unroll
        for (int ks = 0; ks < 4; ++ks) {
            const int kbase = ks * 8;
            uint32_t a[2][4];
            #pragma unroll
            for (int mm = 0; mm < 2; ++mm) {
                int base = (row0 + mm * 16 + g) * SA + kbase;
                a[mm][0] = As[buf][base + c];
                a[mm][1] = As[buf][base + 8 * SA + c];
                a[mm][2] = As[buf][base + c + 4];
                a[mm][3] = As[buf][base + 8 * SA + c + 4];
            }
            #pragma unroll
            for (int nn = 0; nn < 4; ++nn) {
                int rb = (col0 + nn * 8 + g) * SA + kbase;
                uint32_t b0 = Bs[buf][rb + c];
                uint32_t b1 = Bs[buf][rb + c + 4];
                #pragma unroll
                for (int mm = 0; mm < 2; ++mm) {
                    mma_tf32(acc[mm][nn], a[mm][0], a[mm][1], a[mm][2], a[mm][3],
                             b0, b1);
                }
            }
        }
        __syncthreads();
        buf ^= 1;
    }

    // ---- fused AGRU epilogue ----
    #pragma unroll
    for (int mm = 0; mm < 2; ++mm) {
        int gm0 = bm + row0 + mm * 16 + g;
        #pragma unroll
        for (int nn = 0; nn < 4; ++nn) {
            int gn = bn + col0 + nn * 8 + 2 * c;
            if (gn >= N) continue;
            int d = gn >> 1;
            #pragma unroll
            for (int half = 0; half < 2; ++half) {
                int gm = gm0 + half * 8;
                int frow = gm * KK + t;
                float2 f2 = *reinterpret_cast<const float2*>(fW2 + (size_t)frow * D2 + gn);
                float ur = acc[mm][nn][half * 2 + 0];
                float uh = acc[mm][nn][half * 2 + 1];
                float r = sigm(f2.x + ur);
                float ht = tanhf(f2.y + r * uh);
                float gg = gate[frow];
                float hold = Ain[(size_t)gm * DD + d];
                Hout[(size_t)gm * DD + d] = gg * ht + (1.f - gg) * hold;
            }
        }
    }
}

// ---------------- packing (length sort) ----------------
__global__ void k_sort_init() {
    int i = threadIdx.x;
    if (i < 16) g_cnt[i] = 0;
}
__global__ void k_hist(const int* __restrict__ lens) {
    __shared__ int sh[16];
    if (threadIdx.x < 16) sh[threadIdx.x] = 0;
    __syncthreads();
    int b = blockIdx.x * blockDim.x + threadIdx.x;
    if (b < BSEQ) atomicAdd(&sh[lens[b]], 1);
    __syncthreads();
    if (threadIdx.x < 16 && sh[threadIdx.x])
        atomicAdd(&g_cnt[threadIdx.x], sh[threadIdx.x]);
}
__global__ void k_base() {
    if (threadIdx.x == 0) {
        int off = 0;
        for (int l = LL; l >= 1; --l) {
            g_basec[l] = off;
            g_cursor[l] = off;
            off += g_cnt[l];
        }
        for (int t = 0; t < LL; ++t) {
            int na = g_basec[t + 1] + g_cnt[t + 1];   // #len > t
            g_nact[t] = na;
            g_nact2[t] = na;
            g_nact2[LL + t] = na;
            g_nactpair[2 * t] = na;
            g_nactpair[2 * t + 1] = na;
        }
    }
}
__global__ void k_perm(const int* __restrict__ lens) {
    int b = blockIdx.x * blockDim.x + threadIdx.x;
    if (b < BSEQ) {
        int pos = atomicAdd(&g_cursor[lens[b]], 1);
        g_perm[pos] = b;
    }
}

// pack both dirs: xp[dir*BLTOT + t*BSEQ + pos] = x[perm[pos], srct]
__global__ void k_pack2(const float* __restrict__ x, const int* __restrict__ lens,
                        float* __restrict__ xp)
{
    size_t idx = (size_t)blockIdx.x * blockDim.x + threadIdx.x;
    if (idx >= (size_t)2 * BLTOT * D4) return;
    int d = (int)(idx % D4) * 4;
    size_t row = idx / D4;
    int dir = row >= BLTOT;
    size_t r2 = row - (size_t)dir * BLTOT;
    int t = (int)(r2 >> 14);
    int pos = (int)(r2 & 16383);
    if (pos >= g_nact[t]) return;
    int b = g_perm[pos];
    int srct = dir ? (lens[b] - 1 - t) : t;
    *reinterpret_cast<float4*>(xp + row * DD + d) =
        *reinterpret_cast<const float4*>(x + ((size_t)b * LL + srct) * DD + d);
}

// merged GRU gate update (both dirs), packed rows [0, nact[t])
__global__ void gru_pointwise2(const float* __restrict__ xg, const float* __restrict__ hg,
                               float* __restrict__ h, int t)
{
    int idx = blockIdx.x * blockDim.x + threadIdx.x;
    if (idx >= 2 * BSEQ * D4) return;
    int pos2 = idx / D4;
    int dir = pos2 >> 14;
    int pos = pos2 & 16383;
    if (pos >= g_nact[t]) return;
    int d = (idx - pos2 * D4) * 4;
    const float* xr = xg + ((size_t)dir * BLTOT + (size_t)t * BSEQ + pos) * G3D;
    const float* hr = hg + (size_t)pos2 * G3D;
    float4 xrv = *reinterpret_cast<const float4*>(xr + d);
    float4 xzv = *reinterpret_cast<const float4*>(xr + DD + d);
    float4 xnv = *reinterpret_cast<const float4*>(xr + 2 * DD + d);
    float4 hrv = *reinterpret_cast<const float4*>(hr + d);
    float4 hzv = *reinterpret_cast<const float4*>(hr + DD + d);
    float4 hnv = *reinterpret_cast<const float4*>(hr + 2 * DD + d);
    float4 hv  = *reinterpret_cast<float4*>(h + (size_t)pos2 * DD + d);
    float4 o;
    { float r = sigm(xrv.x + hrv.x), z = sigm(xzv.x + hzv.x);
      float n = tanhf(xnv.x + r * hnv.x); o.x = (1.f - z) * n + z * hv.x; }
    { float r = sigm(xrv.y + hrv.y), z = sigm(xzv.y + hzv.y);
      float n = tanhf(xnv.y + r * hnv.y); o.y = (1.f - z) * n + z * hv.y; }
    { float r = sigm(xrv.z + hrv.z), z = sigm(xzv.z + hzv.z);
      float n = tanhf(xnv.z + r * hnv.z); o.z = (1.f - z) * n + z * hv.z; }
    { float r = sigm(xrv.w + hrv.w), z = sigm(xzv.w + hzv.w);
      float n = tanhf(xnv.w + r * hnv.w); o.w = (1.f - z) * n + z * hv.w; }
    *reinterpret_cast<float4*>(h + (size_t)pos2 * DD + d) = o;
}

// facts[perm[pos]] = h[pos] + h[BSEQ+pos]
__global__ void k_unpack_facts(const float* __restrict__ h, float* __restrict__ facts)
{
    int idx = blockIdx.x * blockDim.x + threadIdx.x;
    if (idx >= BSEQ * D4) return;
    int pos = idx / D4;
    int d = (idx - pos * D4) * 4;
    int b = g_perm[pos];
    float4 a = *reinterpret_cast<const float4*>(h + (size_t)pos * DD + d);
    float4 bb = *reinterpret_cast<const float4*>(h + (size_t)(BSEQ + pos) * DD + d);
    *reinterpret_cast<float4*>(facts + (size_t)b * DD + d) =
        make_float4(a.x + bb.x, a.y + bb.y, a.z + bb.z, a.w + bb.w);
}

// ---------------- misc elementwise ----------------
__global__ void k_zero(float* p, size_t n) {
    size_t i = (size_t)blockIdx.x * blockDim.x + threadIdx.x;
    if (i < n) p[i] = 0.f;
}
__global__ void k_copy(float* dst, const float* src, size_t n) {
    size_t i = (size_t)blockIdx.x * blockDim.x + threadIdx.x;
    if (i < n) dst[i] = src[i];
}

// interleave rows: out[2d+g] = (g ? Xh : Xr)[d]  (rows DD x cols DD)
__global__ void k_interleave(const float* __restrict__ Xr, const float* __restrict__ Xh,
                             float* __restrict__ out)
{
    int idx = blockIdx.x * blockDim.x + threadIdx.x;
    if (idx >= D2 * DD) return;
    int row = idx / DD, k = idx - row * DD;
    int d = row >> 1;
    out[idx] = (row & 1) ? Xh[d * DD + k] : Xr[d * DD + k];
}
__global__ void k_interleave_b(const float* __restrict__ br, const float* __restrict__ bh,
                               float* __restrict__ out)
{
    int i = threadIdx.x + blockIdx.x * blockDim.x;
    if (i >= D2) return;
    out[i] = (i & 1) ? bh[i >> 1] : br[i >> 1];
}

__global__ void k_gather_feats(const float* __restrict__ pooled, const int* __restrict__ vidx,
                               float* __restrict__ feats)
{
    int idx = blockIdx.x * blockDim.x + threadIdx.x;
    if (idx >= NVOBJ * (FF / 4)) return;
    int v = idx / (FF / 4), j = (idx - v * (FF / 4)) * 4;
    *reinterpret_cast<float4*>(feats + (size_t)v * FF + j) =
        *reinterpret_cast<const float4*>(pooled + (size_t)vidx[v] * FF + j);
}

__global__ void k_build_z(const float* __restrict__ facts, const float* __restrict__ q,
                          const float* __restrict__ m, float* __restrict__ z)
{
    size_t idx = (size_t)blockIdx.x * blockDim.x + threadIdx.x;
    if (idx >= (size_t)BSEQ * DD) return;
    int d = idx % DD;
    int i = idx / DD;
    int v = i / KK;
    float f = facts[idx];
    float qv = q[(size_t)v * DD + d];
    float mv = m[(size_t)v * DD + d];
    float* zr = z + (size_t)i * ZDIM;
    zr[d] = f * qv;
    zr[DD + d] = f * mv;
    zr[2 * DD + d] = fabsf(f - qv);
    zr[3 * DD + d] = fabsf(f - mv);
}

__global__ void k_score_softmax(const float* __restrict__ h1, const float* __restrict__ w2,
                                const float* __restrict__ w2b, float* __restrict__ gate)
{
    int v = blockIdx.x;
    int tid = threadIdx.x;
    int w = tid >> 5, lane = tid & 31;
    __shared__ float s[KK];
    const float* row = h1 + ((size_t)v * KK + w) * FF;
    float sum = 0.f;
    for (int j = lane; j < FF; j += 32) sum += row[j] * w2[j];
    #pragma unroll
    for (int o = 16; o > 0; o >>= 1) sum += __shfl_down_sync(0xffffffffu, sum, o);
    if (lane == 0) s[w] = sum + w2b[0];
    __syncthreads();
    if (tid == 0) {
        float mx = s[0];
        #pragma unroll
        for (int k = 1; k < KK; k++) mx = fmaxf(mx, s[k]);
        float tot = 0.f, e[KK];
        #pragma unroll
        for (int k = 0; k < KK; k++) { e[k] = expf(s[k] - mx); tot += e[k]; }
        #pragma unroll
        for (int k = 0; k < KK; k++) gate[v * KK + k] = e[k] / tot;
    }
}

__global__ void k_cat3(const float* __restrict__ m, const float* __restrict__ attn,
                       const float* __restrict__ q, float* __restrict__ cat)
{
    int idx = blockIdx.x * blockDim.x + threadIdx.x;
    if (idx >= NVOBJ * G3D) return;
    int v = idx / G3D, c = idx - v * G3D;
    float val;
    if (c < DD)           val = m[v * DD + c];
    else if (c < 2 * DD)  val = attn[v * DD + c - DD];
    else                  val = q[v * DD + c - 2 * DD];
    cat[idx] = val;
}

__global__ void k_cat2(const float* __restrict__ feats, const float* __restrict__ m,
                       float* __restrict__ cat)
{
    int idx = blockIdx.x * blockDim.x + threadIdx.x;
    if (idx >= NVOBJ * CAT2) return;
    int v = idx / CAT2, c = idx - v * CAT2;
    cat[idx] = (c < FF) ? feats[v * FF + c] : m[v * DD + (c - FF)];
}

__global__ void k_scatter(const float* __restrict__ upd, const int* __restrict__ vidx,
                          float* __restrict__ out)
{
    int idx = blockIdx.x * blockDim.x + threadIdx.x;
    if (idx >= NVOBJ * FF) return;
    int v = idx / FF, j = idx - v * FF;
    out[(size_t)vidx[v] * FF + j] = upd[idx];
}

// ---------------- host orchestration ----------------
static inline dim3 gemm_grid(int M, int N) {
    return dim3((N + 63) / 64, (M + 127) / 128);
}
#define EWG(n) ((int)(((n) + 255) / 256))

extern "C" void kernel_launch(void* const* d_in, const int* in_sizes, int n_in,
                              void* d_out, int out_size)
{
    const float* pooled  = (const float*)d_in[0];
    const float* concept = (const float*)d_in[1];
    const int*   seqlen  = (const int*)d_in[2];
    const int*   vidx    = (const int*)d_in[3];
    const float* Wih     = (const float*)d_in[4];
    const float* Whh     = (const float*)d_in[5];
    const float* bih     = (const float*)d_in[6];
    const float* bhh     = (const float*)d_in[7];
    const float* Wq_w    = (const float*)d_in[8];
    const float* Wq_b    = (const float*)d_in[9];
    const float* W1_w    = (const float*)d_in[10];
    const float* W1_b    = (const float*)d_in[11];
    const float* W2_w    = (const float*)d_in[12];
    const float* W2_b    = (const float*)d_in[13];
    const float* aWr     = (const float*)d_in[14];
    const float* aUr     = (const float*)d_in[15];
    const float* abr     = (const float*)d_in[16];
    const float* aWh     = (const float*)d_in[17];
    const float* aUh     = (const float*)d_in[18];
    const float* abh     = (const float*)d_in[19];
    const float* nmt_w   = (const float*)d_in[20];
    const float* nmt_b   = (const float*)d_in[21];
    const float* upd_w   = (const float*)d_in[22];
    const float* upd_b   = (const float*)d_in[23];
    float* out = (float*)d_out;

    float *xg, *xp, *hg, *h, *facts, *feats, *q, *m, *z, *h1, *gate;
    float *U2i, *W2i, *b2i, *fW2, *attnA, *attnB, *cat, *cat2, *upd;
    int *nact, *nact2, *nactpair;
    cudaGetSymbolAddress((void**)&xg, g_xg);
    cudaGetSymbolAddress((void**)&xp, g_xp);
    cudaGetSymbolAddress((void**)&hg, g_hg);
    cudaGetSymbolAddress((void**)&h, g_h);
    cudaGetSymbolAddress((void**)&facts, g_facts);
    cudaGetSymbolAddress((void**)&feats, g_feats);
    cudaGetSymbolAddress((void**)&q, g_q);
    cudaGetSymbolAddress((void**)&m, g_m);
    cudaGetSymbolAddress((void**)&z, g_z);
    cudaGetSymbolAddress((void**)&h1, g_h1);
    cudaGetSymbolAddress((void**)&gate, g_gate);
    cudaGetSymbolAddress((void**)&U2i, g_U2i);
    cudaGetSymbolAddress((void**)&W2i, g_W2i);
    cudaGetSymbolAddress((void**)&b2i, g_b2i);
    cudaGetSymbolAddress((void**)&fW2, g_fW2);
    cudaGetSymbolAddress((void**)&attnA, g_attnA);
    cudaGetSymbolAddress((void**)&attnB, g_attnB);
    cudaGetSymbolAddress((void**)&cat, g_cat);
    cudaGetSymbolAddress((void**)&cat2, g_cat2);
    cudaGetSymbolAddress((void**)&upd, g_upd);
    cudaGetSymbolAddress((void**)&nact, g_nact);
    cudaGetSymbolAddress((void**)&nact2, g_nact2);
    cudaGetSymbolAddress((void**)&nactpair, g_nactpair);

    // ===== length sort / packing metadata =====
    k_sort_init<<<1, 32>>>();
    k_hist<<<EWG(BSEQ), 256>>>(seqlen);
    k_base<<<1, 32>>>();
    k_perm<<<EWG(BSEQ), 256>>>(seqlen);

    // ===== bidirectional GRU, both dirs batched =====
    k_pack2<<<EWG((size_t)2 * BLTOT * D4), 256>>>(concept, seqlen, xp);
    // input projection for both dirs in one GEMM (rows >= BLTOT use dir-1 weights)
    gemm_nt_tc<<<gemm_grid(2 * BLTOT, G3D), 256>>>(
        xp, Wih, bih, xg, 2 * BLTOT, G3D, DD, 0,
        nact2, 14, Wih + (size_t)G3D * DD, bih + G3D, BLTOT);
    k_zero<<<EWG(2 * BSEQ * DD), 256>>>(h, (size_t)2 * BSEQ * DD);
    for (int t = 0; t < LL; ++t) {
        gemm_nt_tc<<<gemm_grid(2 * BSEQ, G3D), 256>>>(
            h, Whh, bhh, hg, 2 * BSEQ, G3D, DD, 0,
            nactpair + 2 * t, 14, Whh + (size_t)G3D * DD, bhh + G3D, BSEQ);
        gru_pointwise2<<<EWG(2 * BSEQ * D4), 256>>>(xg, hg, h, t);
    }
    k_unpack_facts<<<EWG(BSEQ * D4), 256>>>(h, facts);

    // ===== query =====
    k_gather_feats<<<EWG(NVOBJ * (FF / 4)), 256>>>(pooled, vidx, feats);
    gemm_nt_tc<<<gemm_grid(NVOBJ, DD), 256>>>(feats, Wq_w, Wq_b, q,
                                              NVOBJ, DD, FF, 1,
                                              nullptr, 0, nullptr, nullptr, 0);
    k_copy<<<EWG(NVOBJ * DD), 256>>>(m, q, (size_t)NVOBJ * DD);

    // ===== interleaved AGRU weights (r,h pairs) =====
    k_interleave<<<EWG(D2 * DD), 256>>>(aWr, aWh, W2i);
    k_interleave<<<EWG(D2 * DD), 256>>>(aUr, aUh, U2i);
    k_interleave_b<<<EWG(D2), 256>>>(abr, abh, b2i);

    // fW2 = facts @ W2i^T + b2i  (cols 2d,2d+1 = (r_pre, h_pre))
    gemm_nt_tc<<<gemm_grid(BSEQ, D2), 256>>>(facts, W2i, b2i, fW2,
                                             BSEQ, D2, DD, 0,
                                             nullptr, 0, nullptr, nullptr, 0);

    // ===== episodic memory passes =====
    for (int it = 0; it < TM; ++it) {
        k_build_z<<<EWG((size_t)BSEQ * DD), 256>>>(facts, q, m, z);
        gemm_nt_tc<<<gemm_grid(BSEQ, FF), 256>>>(z, W1_w, W1_b, h1,
                                                 BSEQ, FF, ZDIM, 1,
                                                 nullptr, 0, nullptr, nullptr, 0);
        k_score_softmax<<<NVOBJ, 256>>>(h1, W2_w, W2_b, gate);
        k_zero<<<EWG(NVOBJ * DD), 256>>>(attnA, (size_t)NVOBJ * DD);
        for (int t = 0; t < KK; ++t) {
            const float* src = (t & 1) ? attnB : attnA;
            float* dst = (t & 1) ? attnA : attnB;
            gemm_agru<<<dim3((D2 + 63) / 64, (NVOBJ + 127) / 128), 256>>>(
                src, U2i, fW2, gate, dst, t);
        }
        // KK=8 even -> final attn in attnA
        k_cat3<<<EWG(NVOBJ * G3D), 256>>>(m, attnA, q, cat);
        gemm_nt_tc<<<gemm_grid(NVOBJ, DD), 256>>>(cat, nmt_w, nmt_b, m,
                                                  NVOBJ, DD, G3D, 2,
                                                  nullptr, 0, nullptr, nullptr, 0);
    }

    // ===== object update + scatter into output =====
    k_cat2<<<EWG(NVOBJ * CAT2), 256>>>(feats, m, cat2);
    gemm_nt_tc<<<gemm_grid(NVOBJ, FF), 256>>>(cat2, upd_w, upd_b, upd,
                                              NVOBJ, FF, CAT2, 2,
                                              nullptr, 0, nullptr, nullptr, 0);
    k_copy<<<EWG((size_t)NOBJ * FF), 256>>>(out, pooled, (size_t)NOBJ * FF);
    k_scatter<<<EWG(NVOBJ * FF), 256>>>(upd, vidx, out);
}